// round 5
// baseline (speedup 1.0000x reference)
#include <cuda_runtime.h>

#define TT 50
#define NUSERS 4096
#define NDOCS 50
#define DD 64
#define LU 32
#define ZDIM 128   // 4 * LSTM_UNITS, also FC1 width
#define X1STRIDE 132   // padded x1 row (floats), multiple of 4

// -------- device scratch (no allocations allowed) --------
__device__ float g_P[(NDOCS + 1) * ZDIM];      // doc_embed @ Wx[0:64] + lstm_b
__device__ __align__(16) float g_dpart[NDOCS * ZDIM];  // doc_feat @ n1_W[64:128] + n1_b
__device__ float g_h[NUSERS * LU];             // final LSTM hidden states

__device__ __forceinline__ float sigf(float x) { return 1.0f / (1.0f + __expf(-x)); }
__device__ __forceinline__ float tanhfast(float x) { return 2.0f / (1.0f + __expf(-2.0f * x)) - 1.0f; }

// ---------------- K0: precompute P and d_part ----------------
__global__ void precompute_kernel(const float* __restrict__ doc_embed,
                                  const float* __restrict__ lstm_Wx,
                                  const float* __restrict__ lstm_b,
                                  const float* __restrict__ doc_prop,
                                  const float* __restrict__ n1_W,
                                  const float* __restrict__ n1_b) {
    int col = threadIdx.x;   // 0..127
    int b = blockIdx.x;      // 0..100
    if (b <= NDOCS) {
        float acc = lstm_b[col];
#pragma unroll 8
        for (int k = 0; k < DD; k++)
            acc = fmaf(doc_embed[b * DD + k], lstm_Wx[k * ZDIM + col], acc);
        g_P[b * ZDIM + col] = acc;
    } else {
        int d = b - (NDOCS + 1);   // 0..49
        float acc = n1_b[col];
#pragma unroll 8
        for (int k = 0; k < DD; k++)
            acc = fmaf(doc_prop[(d + 1) * DD + k], n1_W[(DD + k) * ZDIM + col], acc);
        g_dpart[d * ZDIM + col] = acc;
    }
}

// ---------------- K1: LSTM, warp = user, lane = unit ----------------
__global__ __launch_bounds__(128, 3)
void lstm_kernel(const int* __restrict__ doc_ids,
                 const float* __restrict__ ctime,
                 const float* __restrict__ lstm_Wh,
                 const float* __restrict__ lstm_Wx) {
    const int lane = threadIdx.x & 31;
    const int u = blockIdx.x * 4 + (threadIdx.x >> 5);

    // Wh columns for this lane's 4 gates, cached in registers (128 regs)
    float wh[LU][4];
#pragma unroll
    for (int k = 0; k < LU; k++)
#pragma unroll
        for (int g = 0; g < 4; g++)
            wh[k][g] = lstm_Wh[k * ZDIM + g * 32 + lane];

    float wlast[4];
#pragma unroll
    for (int g = 0; g < 4; g++)
        wlast[g] = lstm_Wx[DD * ZDIM + g * 32 + lane];

    const int* ids = doc_ids + u * TT;
    const float* cts = ctime + u * TT;

    int id = __ldg(&ids[0]);
    float ctn = __ldg(&cts[0]);

    float h = 0.0f, c = 0.0f;
#pragma unroll 1
    for (int t = 0; t < TT; t++) {
        // issue the P-row gather early; its latency is hidden under the shfl/FMA loop
        const float* Prow = g_P + id * ZDIM + lane;
        float p0 = __ldg(Prow + 0);
        float p1 = __ldg(Prow + 32);
        float p2 = __ldg(Prow + 64);
        float p3 = __ldg(Prow + 96);
        float ct = ctn;
        if (t + 1 < TT) {
            id = __ldg(&ids[t + 1]);
            ctn = __ldg(&cts[t + 1]);
        }
        float z0 = ct * wlast[0];
        float z1 = ct * wlast[1];
        float z2 = ct * wlast[2];
        float z3 = ct * wlast[3];
#pragma unroll
        for (int k = 0; k < LU; k++) {
            float hk = __shfl_sync(0xffffffffu, h, k);
            z0 = fmaf(hk, wh[k][0], z0);
            z1 = fmaf(hk, wh[k][1], z1);
            z2 = fmaf(hk, wh[k][2], z2);
            z3 = fmaf(hk, wh[k][3], z3);
        }
        z0 += p0; z1 += p1; z2 += p2; z3 += p3;
        float gi = sigf(z0);
        float gf = sigf(z1);
        float gg = tanhfast(z2);
        float go = sigf(z3);
        c = fmaf(gf, c, gi * gg);
        h = go * tanhfast(c);
    }
    g_h[u * LU + lane] = h;
}

// ---------------- K2: per-user head + Q-net + slate aggregation ----------------
__global__ __launch_bounds__(256)
void user_kernel(const float* __restrict__ d1_W, const float* __restrict__ d1_b,
                 const float* __restrict__ he_W, const float* __restrict__ he_b,
                 const float* __restrict__ n1_W,
                 const float* __restrict__ n2_W, const float* __restrict__ n2_b,
                 const float* __restrict__ q_W, const float* __restrict__ q_b,
                 const float* __restrict__ doc_prop,
                 const int* __restrict__ slates, int n_slates,
                 float* __restrict__ out) {
    __shared__ __align__(16) float x1s[NDOCS * X1STRIDE];  // relu(u_part + d_part)
    __shared__ __align__(16) float w2s[ZDIM * 32];         // n2_W row-major [k][c]
    __shared__ __align__(16) float ups[ZDIM];
    __shared__ float ue[DD];
    __shared__ float t1[LU];
    __shared__ float hs[LU];
    __shared__ float ss[NDOCS];
    __shared__ float ps[NDOCS];
    __shared__ float qss[NDOCS];
    __shared__ float qw[32];
    __shared__ float n2bs[32];

    const int tid = threadIdx.x;
    const int u = blockIdx.x;

    if (tid < LU) hs[tid] = g_h[u * LU + tid];
    if (tid >= 32 && tid < 64) qw[tid - 32] = q_W[tid - 32];
    if (tid >= 64 && tid < 96) n2bs[tid - 64] = n2_b[tid - 64];
    {
        const float4* src = (const float4*)n2_W;
        float4* dst = (float4*)w2s;
        for (int i = tid; i < ZDIM * 32 / 4; i += 256) dst[i] = src[i];
    }
    __syncthreads();

    // t1 = leaky_relu(h @ d1_W + d1_b)
    if (tid < LU) {
        float acc = d1_b[tid];
#pragma unroll
        for (int k = 0; k < LU; k++) acc = fmaf(hs[k], d1_W[k * LU + tid], acc);
        t1[tid] = acc >= 0.0f ? acc : 0.3f * acc;
    }
    __syncthreads();

    // ue = t1 @ he_W + he_b
    if (tid < DD) {
        float acc = he_b[tid];
#pragma unroll
        for (int k = 0; k < LU; k++) acc = fmaf(t1[k], he_W[k * DD + tid], acc);
        ue[tid] = acc;
    }
    __syncthreads();

    // u_part = ue @ n1_W[0:64]  |  s = exp(ue . doc_feat)
    if (tid < ZDIM) {
        float acc = 0.0f;
#pragma unroll 8
        for (int k = 0; k < DD; k++) acc = fmaf(ue[k], n1_W[k * ZDIM + tid], acc);
        ups[tid] = acc;
    } else if (tid < ZDIM + NDOCS) {
        int d = tid - ZDIM;
        const float* df = doc_prop + (d + 1) * DD;
        float acc = 0.0f;
#pragma unroll 8
        for (int k = 0; k < DD; k++) acc = fmaf(ue[k], __ldg(&df[k]), acc);
        ss[d] = __expf(acc);
    }
    __syncthreads();

    // x1[d][k] = relu(u_part[k] + d_part[d][k])   (float4 path)
    {
        const float4* dp4 = (const float4*)g_dpart;
        const float4* up4 = (const float4*)ups;
        float4* x14 = (float4*)x1s;
        for (int i = tid; i < NDOCS * (ZDIM / 4); i += 256) {
            int d = i >> 5, kq = i & 31;
            float4 v = dp4[i];
            float4 uu = up4[kq];
            v.x = fmaxf(v.x + uu.x, 0.0f);
            v.y = fmaxf(v.y + uu.y, 0.0f);
            v.z = fmaxf(v.z + uu.z, 0.0f);
            v.w = fmaxf(v.w + uu.w, 0.0f);
            x14[d * (X1STRIDE / 4) + kq] = v;
        }
    }
    __syncthreads();

    // x2 = relu(x1 @ n2_W + n2_b); qs = x2 . q_W
    // ALL 256 threads participate (8 full warps -> shfl masks legal).
    // tx = col-group (4 contiguous cols), ty = 0..31; ty >= 25 recomputes
    // clamped duplicate docs and its result is discarded at the store.
    {
        const int tx = tid & 7;
        const int ty = tid >> 3;
        const int tyc = ty < 25 ? ty : ty - 25;   // clamp into [0,25)
        const int d0 = tyc, d1 = tyc + 25;
        const float4* a0 = (const float4*)(x1s + d0 * X1STRIDE);
        const float4* a1 = (const float4*)(x1s + d1 * X1STRIDE);
        const float4* bw = (const float4*)(w2s) + tx;   // w2s[k*32 + tx*4]
        float acc0x = 0.f, acc0y = 0.f, acc0z = 0.f, acc0w = 0.f;
        float acc1x = 0.f, acc1y = 0.f, acc1z = 0.f, acc1w = 0.f;
#pragma unroll 8
        for (int kq = 0; kq < ZDIM / 4; kq++) {
            float4 va0 = a0[kq];
            float4 va1 = a1[kq];
            float4 b0 = bw[(4 * kq + 0) * 8];
            float4 b1 = bw[(4 * kq + 1) * 8];
            float4 b2 = bw[(4 * kq + 2) * 8];
            float4 b3 = bw[(4 * kq + 3) * 8];
            acc0x = fmaf(va0.x, b0.x, acc0x); acc0y = fmaf(va0.x, b0.y, acc0y);
            acc0z = fmaf(va0.x, b0.z, acc0z); acc0w = fmaf(va0.x, b0.w, acc0w);
            acc1x = fmaf(va1.x, b0.x, acc1x); acc1y = fmaf(va1.x, b0.y, acc1y);
            acc1z = fmaf(va1.x, b0.z, acc1z); acc1w = fmaf(va1.x, b0.w, acc1w);
            acc0x = fmaf(va0.y, b1.x, acc0x); acc0y = fmaf(va0.y, b1.y, acc0y);
            acc0z = fmaf(va0.y, b1.z, acc0z); acc0w = fmaf(va0.y, b1.w, acc0w);
            acc1x = fmaf(va1.y, b1.x, acc1x); acc1y = fmaf(va1.y, b1.y, acc1y);
            acc1z = fmaf(va1.y, b1.z, acc1z); acc1w = fmaf(va1.y, b1.w, acc1w);
            acc0x = fmaf(va0.z, b2.x, acc0x); acc0y = fmaf(va0.z, b2.y, acc0y);
            acc0z = fmaf(va0.z, b2.z, acc0z); acc0w = fmaf(va0.z, b2.w, acc0w);
            acc1x = fmaf(va1.z, b2.x, acc1x); acc1y = fmaf(va1.z, b2.y, acc1y);
            acc1z = fmaf(va1.z, b2.z, acc1z); acc1w = fmaf(va1.z, b2.w, acc1w);
            acc0x = fmaf(va0.w, b3.x, acc0x); acc0y = fmaf(va0.w, b3.y, acc0y);
            acc0z = fmaf(va0.w, b3.z, acc0z); acc0w = fmaf(va0.w, b3.w, acc0w);
            acc1x = fmaf(va1.w, b3.x, acc1x); acc1y = fmaf(va1.w, b3.y, acc1y);
            acc1z = fmaf(va1.w, b3.z, acc1z); acc1w = fmaf(va1.w, b3.w, acc1w);
        }
        const int c0 = tx * 4;
        float qp0 = fmaxf(acc0x + n2bs[c0 + 0], 0.f) * qw[c0 + 0];
        qp0 = fmaf(fmaxf(acc0y + n2bs[c0 + 1], 0.f), qw[c0 + 1], qp0);
        qp0 = fmaf(fmaxf(acc0z + n2bs[c0 + 2], 0.f), qw[c0 + 2], qp0);
        qp0 = fmaf(fmaxf(acc0w + n2bs[c0 + 3], 0.f), qw[c0 + 3], qp0);
        float qp1 = fmaxf(acc1x + n2bs[c0 + 0], 0.f) * qw[c0 + 0];
        qp1 = fmaf(fmaxf(acc1y + n2bs[c0 + 1], 0.f), qw[c0 + 1], qp1);
        qp1 = fmaf(fmaxf(acc1z + n2bs[c0 + 2], 0.f), qw[c0 + 2], qp1);
        qp1 = fmaf(fmaxf(acc1w + n2bs[c0 + 3], 0.f), qw[c0 + 3], qp1);
        // reduce over tx (low 3 lane bits) — all warps fully active
        qp0 += __shfl_xor_sync(0xffffffffu, qp0, 1);
        qp0 += __shfl_xor_sync(0xffffffffu, qp0, 2);
        qp0 += __shfl_xor_sync(0xffffffffu, qp0, 4);
        qp1 += __shfl_xor_sync(0xffffffffu, qp1, 1);
        qp1 += __shfl_xor_sync(0xffffffffu, qp1, 2);
        qp1 += __shfl_xor_sync(0xffffffffu, qp1, 4);
        if (tx == 0 && ty < 25) {
            qss[d0] = qp0;
            qss[d1] = qp1;
        }
    }
    __syncthreads();

    if (tid < NDOCS) ps[tid] = ss[tid] * (qss[tid] + q_b[0]);
    __syncthreads();

    // slate aggregation: out[u][si] = (p_i + p_j) / (s_i + s_j + 1)
    float* orow = out + (size_t)u * (size_t)n_slates;
    for (int si = tid; si < n_slates; si += 256) {
        int i0 = __ldg(&slates[2 * si]);
        int i1 = __ldg(&slates[2 * si + 1]);
        float num = ps[i0] + ps[i1];
        float den = ss[i0] + ss[i1] + 1.0f;
        __stcs(&orow[si], __fdividef(num, den));
    }
}

extern "C" void kernel_launch(void* const* d_in, const int* in_sizes, int n_in,
                              void* d_out, int out_size) {
    const int*   doc_ids   = (const int*)d_in[0];
    const float* ctime     = (const float*)d_in[1];
    const int*   slates    = (const int*)d_in[2];
    const float* doc_embed = (const float*)d_in[3];
    const float* doc_prop  = (const float*)d_in[4];
    const float* Wx        = (const float*)d_in[5];
    const float* Wh        = (const float*)d_in[6];
    const float* lb        = (const float*)d_in[7];
    const float* d1W       = (const float*)d_in[8];
    const float* d1b       = (const float*)d_in[9];
    const float* heW       = (const float*)d_in[10];
    const float* heb       = (const float*)d_in[11];
    const float* n1W       = (const float*)d_in[12];
    const float* n1b       = (const float*)d_in[13];
    const float* n2W       = (const float*)d_in[14];
    const float* n2b       = (const float*)d_in[15];
    const float* qW        = (const float*)d_in[16];
    const float* qb        = (const float*)d_in[17];
    const int n_slates = in_sizes[2] / 2;

    precompute_kernel<<<2 * NDOCS + 1, ZDIM>>>(doc_embed, Wx, lb, doc_prop, n1W, n1b);
    lstm_kernel<<<NUSERS / 4, 128>>>(doc_ids, ctime, Wh, Wx);
    user_kernel<<<NUSERS, 256>>>(d1W, d1b, heW, heb, n1W, n2W, n2b, qW, qb,
                                 doc_prop, slates, n_slates, (float*)d_out);
}

// round 6
// speedup vs baseline: 1.0668x; 1.0668x over previous
#include <cuda_runtime.h>

#define TT 50
#define NUSERS 4096
#define NDOCS 50
#define DD 64
#define LU 32
#define ZDIM 128   // 4 * LSTM_UNITS, also FC1 width
#define X1STRIDE 132   // padded x1 row (floats), multiple of 4

typedef unsigned long long u64;

// -------- packed fp32x2 helpers (sm_100a FFMA2 path) --------
__device__ __forceinline__ u64 pack2(float lo, float hi) {
    u64 r; asm("mov.b64 %0, {%1, %2};" : "=l"(r) : "f"(lo), "f"(hi)); return r;
}
__device__ __forceinline__ u64 dup2(float x) { return pack2(x, x); }
__device__ __forceinline__ void unpack2(u64 v, float& lo, float& hi) {
    asm("mov.b64 {%0, %1}, %2;" : "=f"(lo), "=f"(hi) : "l"(v));
}
__device__ __forceinline__ u64 ffma2(u64 a, u64 b, u64 c) {
    u64 d; asm("fma.rn.f32x2 %0, %1, %2, %3;" : "=l"(d) : "l"(a), "l"(b), "l"(c)); return d;
}

// -------- device scratch (no allocations allowed) --------
// g_P layout: [id][lane][gate] — one LDG.128 per lane per step, pairs pre-adjacent
__device__ __align__(16) float g_P[(NDOCS + 1) * ZDIM];
__device__ __align__(16) float g_dpart[NDOCS * ZDIM];  // doc_feat @ n1_W[64:128] + n1_b
__device__ float g_h[NUSERS * LU];                     // final LSTM hidden states

__device__ __forceinline__ float sigf(float x) { return 1.0f / (1.0f + __expf(-x)); }
__device__ __forceinline__ float tanhfast(float x) { return 2.0f / (1.0f + __expf(-2.0f * x)) - 1.0f; }

// ---------------- K0: precompute P (lane-gate layout) and d_part ----------------
__global__ void precompute_kernel(const float* __restrict__ doc_embed,
                                  const float* __restrict__ lstm_Wx,
                                  const float* __restrict__ lstm_b,
                                  const float* __restrict__ doc_prop,
                                  const float* __restrict__ n1_W,
                                  const float* __restrict__ n1_b) {
    int c = threadIdx.x;     // 0..127
    int b = blockIdx.x;      // 0..100
    if (b <= NDOCS) {
        int lane = c >> 2, g = c & 3;
        int col = g * 32 + lane;            // original Wx column
        float acc = lstm_b[col];
#pragma unroll 8
        for (int k = 0; k < DD; k++)
            acc = fmaf(doc_embed[b * DD + k], lstm_Wx[k * ZDIM + col], acc);
        g_P[b * ZDIM + c] = acc;            // [id][lane][gate]
    } else {
        int d = b - (NDOCS + 1);   // 0..49
        float acc = n1_b[c];
#pragma unroll 8
        for (int k = 0; k < DD; k++)
            acc = fmaf(doc_prop[(d + 1) * DD + k], n1_W[(DD + k) * ZDIM + c], acc);
        g_dpart[d * ZDIM + c] = acc;
    }
}

// ---------------- K1: LSTM, warp = user, lane = unit, packed f32x2 gates ----------------
__global__ __launch_bounds__(128, 3)
void lstm_kernel(const int* __restrict__ doc_ids,
                 const float* __restrict__ ctime,
                 const float* __restrict__ lstm_Wh,
                 const float* __restrict__ lstm_Wx) {
    const int lane = threadIdx.x & 31;
    const int u = blockIdx.x * 4 + (threadIdx.x >> 5);

    // packed Wh columns: whp[k][0] = gates(0,1), whp[k][1] = gates(2,3)
    u64 whp[LU][2];
#pragma unroll
    for (int k = 0; k < LU; k++) {
        whp[k][0] = pack2(lstm_Wh[k * ZDIM + lane], lstm_Wh[k * ZDIM + 32 + lane]);
        whp[k][1] = pack2(lstm_Wh[k * ZDIM + 64 + lane], lstm_Wh[k * ZDIM + 96 + lane]);
    }
    const u64 wl01 = pack2(lstm_Wx[DD * ZDIM + lane], lstm_Wx[DD * ZDIM + 32 + lane]);
    const u64 wl23 = pack2(lstm_Wx[DD * ZDIM + 64 + lane], lstm_Wx[DD * ZDIM + 96 + lane]);

    const int* ids = doc_ids + u * TT;
    const float* cts = ctime + u * TT;

    int id = __ldg(&ids[0]);
    float ctn = __ldg(&cts[0]);

    float h = 0.0f, c = 0.0f;
#pragma unroll 1
    for (int t = 0; t < TT; t++) {
        // one LDG.128: this lane's 4 gate biases for doc `id`
        const ulonglong2 pp = *(const ulonglong2*)(g_P + id * ZDIM + lane * 4);
        float ct = ctn;
        if (t + 1 < TT) {
            id = __ldg(&ids[t + 1]);
            ctn = __ldg(&cts[t + 1]);
        }
        u64 ctd = dup2(ct);
        u64 z01 = ffma2(ctd, wl01, pp.x);
        u64 z23 = ffma2(ctd, wl23, pp.y);
#pragma unroll
        for (int k = 0; k < LU; k++) {
            float hk = __shfl_sync(0xffffffffu, h, k);
            u64 hd = dup2(hk);
            z01 = ffma2(hd, whp[k][0], z01);
            z23 = ffma2(hd, whp[k][1], z23);
        }
        float za, zb, zc, zd;
        unpack2(z01, za, zb);
        unpack2(z23, zc, zd);
        float gi = sigf(za);
        float gf = sigf(zb);
        float gg = tanhfast(zc);
        float go = sigf(zd);
        c = fmaf(gf, c, gi * gg);
        h = go * tanhfast(c);
    }
    g_h[u * LU + lane] = h;
}

// ---------------- K2: per-user head + Q-net + slate aggregation ----------------
__global__ __launch_bounds__(256)
void user_kernel(const float* __restrict__ d1_W, const float* __restrict__ d1_b,
                 const float* __restrict__ he_W, const float* __restrict__ he_b,
                 const float* __restrict__ n1_W,
                 const float* __restrict__ n2_W, const float* __restrict__ n2_b,
                 const float* __restrict__ q_W, const float* __restrict__ q_b,
                 const float* __restrict__ doc_prop,
                 const int* __restrict__ slates, int n_slates,
                 float* __restrict__ out) {
    __shared__ __align__(16) float x1s[NDOCS * X1STRIDE];  // relu(u_part + d_part)
    __shared__ __align__(16) float w2s[ZDIM * 32];         // n2_W row-major [k][c]
    __shared__ __align__(16) float ups[ZDIM];
    __shared__ float qpart[NDOCS * 8];                     // per-(doc,tx) q partials
    __shared__ float ue[DD];
    __shared__ float t1[LU];
    __shared__ float hs[LU];
    __shared__ float ss[NDOCS];
    __shared__ float ps[NDOCS];
    __shared__ float qss[NDOCS];
    __shared__ float qw[32];
    __shared__ float n2bs[32];

    const int tid = threadIdx.x;
    const int u = blockIdx.x;

    if (tid < LU) hs[tid] = g_h[u * LU + tid];
    if (tid >= 32 && tid < 64) qw[tid - 32] = q_W[tid - 32];
    if (tid >= 64 && tid < 96) n2bs[tid - 64] = n2_b[tid - 64];
    {
        const float4* src = (const float4*)n2_W;
        float4* dst = (float4*)w2s;
        for (int i = tid; i < ZDIM * 32 / 4; i += 256) dst[i] = src[i];
    }
    __syncthreads();

    // t1 = leaky_relu(h @ d1_W + d1_b)
    if (tid < LU) {
        float acc = d1_b[tid];
#pragma unroll
        for (int k = 0; k < LU; k++) acc = fmaf(hs[k], d1_W[k * LU + tid], acc);
        t1[tid] = acc >= 0.0f ? acc : 0.3f * acc;
    }
    __syncthreads();

    // ue = t1 @ he_W + he_b
    if (tid < DD) {
        float acc = he_b[tid];
#pragma unroll
        for (int k = 0; k < LU; k++) acc = fmaf(t1[k], he_W[k * DD + tid], acc);
        ue[tid] = acc;
    }
    __syncthreads();

    // u_part = ue @ n1_W[0:64]  |  s = exp(ue . doc_feat)
    if (tid < ZDIM) {
        float acc = 0.0f;
#pragma unroll 8
        for (int k = 0; k < DD; k++) acc = fmaf(ue[k], n1_W[k * ZDIM + tid], acc);
        ups[tid] = acc;
    } else if (tid < ZDIM + NDOCS) {
        int d = tid - ZDIM;
        const float* df = doc_prop + (d + 1) * DD;
        float acc = 0.0f;
#pragma unroll 8
        for (int k = 0; k < DD; k++) acc = fmaf(ue[k], __ldg(&df[k]), acc);
        ss[d] = __expf(acc);
    }
    __syncthreads();

    // x1[d][k] = relu(u_part[k] + d_part[d][k])   (float4 path)
    {
        const float4* dp4 = (const float4*)g_dpart;
        const float4* up4 = (const float4*)ups;
        float4* x14 = (float4*)x1s;
        for (int i = tid; i < NDOCS * (ZDIM / 4); i += 256) {
            int d = i >> 5, kq = i & 31;
            float4 v = dp4[i];
            float4 uu = up4[kq];
            v.x = fmaxf(v.x + uu.x, 0.0f);
            v.y = fmaxf(v.y + uu.y, 0.0f);
            v.z = fmaxf(v.z + uu.z, 0.0f);
            v.w = fmaxf(v.w + uu.w, 0.0f);
            x14[d * (X1STRIDE / 4) + kq] = v;
        }
    }
    __syncthreads();

    // x2 = relu(x1 @ n2_W + n2_b); qs = x2 . q_W
    // 200 threads, zero duplication, packed f32x2 accumulators, no warp collectives.
    if (tid < 200) {
        const int tx = tid & 7;        // 4 contiguous cols per thread (as 2 packed pairs)
        const int ty = tid >> 3;       // 0..24; docs {ty, ty+25}
        const int d0 = ty, d1 = ty + 25;
        const float4* a0 = (const float4*)(x1s + d0 * X1STRIDE);
        const float4* a1 = (const float4*)(x1s + d1 * X1STRIDE);
        const ulonglong2* w2v = (const ulonglong2*)w2s;   // [k][8 pairs-of-pairs]
        u64 acc00 = 0ull, acc01v = 0ull;   // doc0: cols (c0,c0+1), (c0+2,c0+3)
        u64 acc10 = 0ull, acc11v = 0ull;   // doc1
#pragma unroll 8
        for (int kq = 0; kq < ZDIM / 4; kq++) {
            float4 va0 = a0[kq];
            float4 va1 = a1[kq];
            ulonglong2 b0 = w2v[(4 * kq + 0) * 8 + tx];
            ulonglong2 b1 = w2v[(4 * kq + 1) * 8 + tx];
            ulonglong2 b2 = w2v[(4 * kq + 2) * 8 + tx];
            ulonglong2 b3 = w2v[(4 * kq + 3) * 8 + tx];
            u64 a;
            a = dup2(va0.x); acc00 = ffma2(a, b0.x, acc00); acc01v = ffma2(a, b0.y, acc01v);
            a = dup2(va1.x); acc10 = ffma2(a, b0.x, acc10); acc11v = ffma2(a, b0.y, acc11v);
            a = dup2(va0.y); acc00 = ffma2(a, b1.x, acc00); acc01v = ffma2(a, b1.y, acc01v);
            a = dup2(va1.y); acc10 = ffma2(a, b1.x, acc10); acc11v = ffma2(a, b1.y, acc11v);
            a = dup2(va0.z); acc00 = ffma2(a, b2.x, acc00); acc01v = ffma2(a, b2.y, acc01v);
            a = dup2(va1.z); acc10 = ffma2(a, b2.x, acc10); acc11v = ffma2(a, b2.y, acc11v);
            a = dup2(va0.w); acc00 = ffma2(a, b3.x, acc00); acc01v = ffma2(a, b3.y, acc01v);
            a = dup2(va1.w); acc10 = ffma2(a, b3.x, acc10); acc11v = ffma2(a, b3.y, acc11v);
        }
        const int c0 = tx * 4;
        float s0, s1, s2, s3;
        unpack2(acc00, s0, s1); unpack2(acc01v, s2, s3);
        float qp0 = fmaxf(s0 + n2bs[c0 + 0], 0.f) * qw[c0 + 0];
        qp0 = fmaf(fmaxf(s1 + n2bs[c0 + 1], 0.f), qw[c0 + 1], qp0);
        qp0 = fmaf(fmaxf(s2 + n2bs[c0 + 2], 0.f), qw[c0 + 2], qp0);
        qp0 = fmaf(fmaxf(s3 + n2bs[c0 + 3], 0.f), qw[c0 + 3], qp0);
        unpack2(acc10, s0, s1); unpack2(acc11v, s2, s3);
        float qp1 = fmaxf(s0 + n2bs[c0 + 0], 0.f) * qw[c0 + 0];
        qp1 = fmaf(fmaxf(s1 + n2bs[c0 + 1], 0.f), qw[c0 + 1], qp1);
        qp1 = fmaf(fmaxf(s2 + n2bs[c0 + 2], 0.f), qw[c0 + 2], qp1);
        qp1 = fmaf(fmaxf(s3 + n2bs[c0 + 3], 0.f), qw[c0 + 3], qp1);
        qpart[d0 * 8 + tx] = qp0;
        qpart[d1 * 8 + tx] = qp1;
    }
    __syncthreads();

    // reduce 8 q-partials per doc
    if (tid < NDOCS) {
        const float* qp = qpart + tid * 8;
        float q = ((qp[0] + qp[1]) + (qp[2] + qp[3])) + ((qp[4] + qp[5]) + (qp[6] + qp[7]));
        qss[tid] = q;
    }
    __syncthreads();

    if (tid < NDOCS) ps[tid] = ss[tid] * (qss[tid] + q_b[0]);
    __syncthreads();

    // slate aggregation: out[u][si] = (p_i + p_j) / (s_i + s_j + 1)
    float* orow = out + (size_t)u * (size_t)n_slates;
    for (int si = tid; si < n_slates; si += 256) {
        int i0 = __ldg(&slates[2 * si]);
        int i1 = __ldg(&slates[2 * si + 1]);
        float num = ps[i0] + ps[i1];
        float den = ss[i0] + ss[i1] + 1.0f;
        __stcs(&orow[si], __fdividef(num, den));
    }
}

extern "C" void kernel_launch(void* const* d_in, const int* in_sizes, int n_in,
                              void* d_out, int out_size) {
    const int*   doc_ids   = (const int*)d_in[0];
    const float* ctime     = (const float*)d_in[1];
    const int*   slates    = (const int*)d_in[2];
    const float* doc_embed = (const float*)d_in[3];
    const float* doc_prop  = (const float*)d_in[4];
    const float* Wx        = (const float*)d_in[5];
    const float* Wh        = (const float*)d_in[6];
    const float* lb        = (const float*)d_in[7];
    const float* d1W       = (const float*)d_in[8];
    const float* d1b       = (const float*)d_in[9];
    const float* heW       = (const float*)d_in[10];
    const float* heb       = (const float*)d_in[11];
    const float* n1W       = (const float*)d_in[12];
    const float* n1b       = (const float*)d_in[13];
    const float* n2W       = (const float*)d_in[14];
    const float* n2b       = (const float*)d_in[15];
    const float* qW        = (const float*)d_in[16];
    const float* qb        = (const float*)d_in[17];
    const int n_slates = in_sizes[2] / 2;

    precompute_kernel<<<2 * NDOCS + 1, ZDIM>>>(doc_embed, Wx, lb, doc_prop, n1W, n1b);
    lstm_kernel<<<NUSERS / 4, 128>>>(doc_ids, ctime, Wh, Wx);
    user_kernel<<<NUSERS, 256>>>(d1W, d1b, heW, heb, n1W, n2W, n2b, qW, qb,
                                 doc_prop, slates, n_slates, (float*)d_out);
}